// round 1
// baseline (speedup 1.0000x reference)
#include <cuda_runtime.h>
#include <math.h>

#define T_TOK 1024
#define HDIM  1024
#define IDIM  512
#define NEXP  64
#define TOPK  8

// ---------------- scratch (static device globals; no allocation) ----------------
__device__ int   g_count[NEXP];
__device__ int   g_assign_tok[NEXP * T_TOK];
__device__ float g_assign_w[NEXP * T_TOK];
__device__ int   g_tok2slot[T_TOK * TOPK];
__device__ float g_sact[T_TOK * IDIM];                         // shared-expert act, 2 MB
__device__ float g_act[(size_t)NEXP * T_TOK * IDIM];           // routed act, 134 MB
__device__ float g_part[(size_t)NEXP * T_TOK * HDIM];          // per-assignment down partials, 268 MB

// ---------------- init ----------------
__global__ void zero_counts_kernel() {
    if (threadIdx.x < NEXP) g_count[threadIdx.x] = 0;
}

// ---------------- router: logits -> sigmoid -> top8 -> normalized weights ----------------
__global__ void router_kernel(const float* __restrict__ x, const float* __restrict__ rw) {
    __shared__ float xs[HDIM];
    __shared__ float aff[NEXP];
    const int t = blockIdx.x;
    const int tid = threadIdx.x; // 64 threads

    for (int h = tid; h < HDIM; h += 64) xs[h] = x[(size_t)t * HDIM + h];
    __syncthreads();

    float acc = 0.f;
#pragma unroll 8
    for (int h = 0; h < HDIM; h++) acc += xs[h] * rw[h * NEXP + tid];
    aff[tid] = 1.f / (1.f + expf(-acc));
    __syncthreads();

    if (tid == 0) {
        float tmp[NEXP];
#pragma unroll
        for (int i = 0; i < NEXP; i++) tmp[i] = aff[i];
        int   idx[TOPK];
        float sc[TOPK];
        float s = 0.f;
        for (int k = 0; k < TOPK; k++) {
            int bi = 0; float bv = -1e30f;
            for (int i = 0; i < NEXP; i++) {
                if (tmp[i] > bv) { bv = tmp[i]; bi = i; }
            }
            idx[k] = bi; sc[k] = bv; tmp[bi] = -1e30f; s += bv;
        }
        const float inv = 1.f / (s + 1e-9f);
        for (int k = 0; k < TOPK; k++) {
            const int e = idx[k];
            const float w = sc[k] * inv;
            const int slot = atomicAdd(&g_count[e], 1);
            g_assign_tok[e * T_TOK + slot] = t;
            g_assign_w[e * T_TOK + slot]   = w;
            g_tok2slot[t * TOPK + k]       = e * T_TOK + slot;
        }
    }
}

// ---------------- shared-expert gate/up (fused SwiGLU): sact = silu(x@Wg) * (x@Wu) ----------------
__global__ __launch_bounds__(256) void shared_gateup_kernel(const float* __restrict__ x,
                                                            const float* __restrict__ gw,
                                                            const float* __restrict__ uw) {
    __shared__ float Xs[16][68];
    __shared__ float Gs[16][64];
    __shared__ float Us[16][64];

    const int ic  = blockIdx.x;          // 0..7 : I-chunk of 64
    const int tc  = blockIdx.y;          // 0..15: token chunk of 64
    const int tid = threadIdx.x;
    const int tx = tid & 15, ty = tid >> 4;

    const int row0 = tc * 64;
    const int ic0  = ic * 64;

    const int arow = tid >> 2;           // 0..63
    const int ak   = (tid & 3) * 4;      // 0,4,8,12
    const int bk   = tid >> 4;           // 0..15
    const int bc   = (tid & 15) * 4;

    float accg[4][4] = {}; float accu[4][4] = {};

    for (int k0 = 0; k0 < HDIM; k0 += 16) {
        float4 xa = *(const float4*)(x  + (size_t)(row0 + arow) * HDIM + k0 + ak);
        float4 ga = *(const float4*)(gw + (size_t)(k0 + bk) * IDIM + ic0 + bc);
        float4 ua = *(const float4*)(uw + (size_t)(k0 + bk) * IDIM + ic0 + bc);
        __syncthreads();
        Xs[ak + 0][arow] = xa.x; Xs[ak + 1][arow] = xa.y;
        Xs[ak + 2][arow] = xa.z; Xs[ak + 3][arow] = xa.w;
        *(float4*)&Gs[bk][bc] = ga;
        *(float4*)&Us[bk][bc] = ua;
        __syncthreads();
#pragma unroll
        for (int kk = 0; kk < 16; kk++) {
            float4 a = *(const float4*)&Xs[kk][ty * 4];
            float4 g = *(const float4*)&Gs[kk][tx * 4];
            float4 u = *(const float4*)&Us[kk][tx * 4];
            float av[4] = {a.x, a.y, a.z, a.w};
            float gv[4] = {g.x, g.y, g.z, g.w};
            float uv[4] = {u.x, u.y, u.z, u.w};
#pragma unroll
            for (int i = 0; i < 4; i++)
#pragma unroll
                for (int j = 0; j < 4; j++) {
                    accg[i][j] += av[i] * gv[j];
                    accu[i][j] += av[i] * uv[j];
                }
        }
    }

#pragma unroll
    for (int i = 0; i < 4; i++) {
        const int r = row0 + ty * 4 + i;
        float4 o;
        float* ov = (float*)&o;
#pragma unroll
        for (int j = 0; j < 4; j++) {
            const float gv = accg[i][j];
            const float sv = gv / (1.f + expf(-gv));
            ov[j] = sv * accu[i][j];
        }
        *(float4*)(g_sact + (size_t)r * IDIM + ic0 + tx * 4) = o;
    }
}

// ---------------- routed gate/up (gathered rows, fused SwiGLU * routing weight) ----------------
__global__ __launch_bounds__(256) void expert_gateup_kernel(const float* __restrict__ x,
                                                            const float* __restrict__ gw,   // [E,H,I]
                                                            const float* __restrict__ uw) { // [E,H,I]
    __shared__ float Xs[16][68];
    __shared__ float Gs[16][64];
    __shared__ float Us[16][64];
    __shared__ int   toks[64];

    const int e  = blockIdx.x >> 3;
    const int ic = blockIdx.x & 7;
    const int tc = blockIdx.y;
    const int n  = g_count[e];
    const int row0 = tc * 64;
    if (row0 >= n) return;

    const int tid = threadIdx.x;
    const int tx = tid & 15, ty = tid >> 4;

    if (tid < 64) {
        const int r = row0 + tid;
        toks[tid] = (r < n) ? g_assign_tok[e * T_TOK + r] : 0;
    }
    __syncthreads();

    const float* gbase = gw + (size_t)e * HDIM * IDIM + ic * 64;
    const float* ubase = uw + (size_t)e * HDIM * IDIM + ic * 64;

    const int arow = tid >> 2;
    const int ak   = (tid & 3) * 4;
    const int bk   = tid >> 4;
    const int bc   = (tid & 15) * 4;
    const int myTok = toks[arow];

    float accg[4][4] = {}; float accu[4][4] = {};

    for (int k0 = 0; k0 < HDIM; k0 += 16) {
        float4 xa = *(const float4*)(x + (size_t)myTok * HDIM + k0 + ak);
        float4 ga = *(const float4*)(gbase + (size_t)(k0 + bk) * IDIM + bc);
        float4 ua = *(const float4*)(ubase + (size_t)(k0 + bk) * IDIM + bc);
        __syncthreads();
        Xs[ak + 0][arow] = xa.x; Xs[ak + 1][arow] = xa.y;
        Xs[ak + 2][arow] = xa.z; Xs[ak + 3][arow] = xa.w;
        *(float4*)&Gs[bk][bc] = ga;
        *(float4*)&Us[bk][bc] = ua;
        __syncthreads();
#pragma unroll
        for (int kk = 0; kk < 16; kk++) {
            float4 a = *(const float4*)&Xs[kk][ty * 4];
            float4 g = *(const float4*)&Gs[kk][tx * 4];
            float4 u = *(const float4*)&Us[kk][tx * 4];
            float av[4] = {a.x, a.y, a.z, a.w};
            float gv[4] = {g.x, g.y, g.z, g.w};
            float uv[4] = {u.x, u.y, u.z, u.w};
#pragma unroll
            for (int i = 0; i < 4; i++)
#pragma unroll
                for (int j = 0; j < 4; j++) {
                    accg[i][j] += av[i] * gv[j];
                    accu[i][j] += av[i] * uv[j];
                }
        }
    }

    int nn = n - row0; if (nn > 64) nn = 64;
    float* actbase = g_act + ((size_t)e * T_TOK + row0) * IDIM + ic * 64;
#pragma unroll
    for (int i = 0; i < 4; i++) {
        const int r = ty * 4 + i;
        if (r < nn) {
            const float w = g_assign_w[e * T_TOK + row0 + r];
            float4 o;
            float* ov = (float*)&o;
#pragma unroll
            for (int j = 0; j < 4; j++) {
                const float gv = accg[i][j];
                const float sv = gv / (1.f + expf(-gv));
                ov[j] = sv * accu[i][j] * w;
            }
            *(float4*)(actbase + (size_t)r * IDIM + tx * 4) = o;
        }
    }
}

// ---------------- shared-expert down: out = sact @ Wd  (writes/initializes d_out) ----------------
__global__ __launch_bounds__(256) void shared_down_kernel(const float* __restrict__ dw,
                                                          float* __restrict__ out) {
    __shared__ float As[16][68];
    __shared__ float Bs[16][64];

    const int hc = blockIdx.x;           // 0..15: H chunk of 64
    const int tc = blockIdx.y;           // 0..15: token chunk of 64
    const int tid = threadIdx.x;
    const int tx = tid & 15, ty = tid >> 4;

    const int row0 = tc * 64;
    const int hc0  = hc * 64;

    const int arow = tid >> 2;
    const int ak   = (tid & 3) * 4;
    const int bk   = tid >> 4;
    const int bc   = (tid & 15) * 4;

    float acc[4][4] = {};

    for (int k0 = 0; k0 < IDIM; k0 += 16) {
        float4 aa = *(const float4*)(g_sact + (size_t)(row0 + arow) * IDIM + k0 + ak);
        float4 ba = *(const float4*)(dw + (size_t)(k0 + bk) * HDIM + hc0 + bc);
        __syncthreads();
        As[ak + 0][arow] = aa.x; As[ak + 1][arow] = aa.y;
        As[ak + 2][arow] = aa.z; As[ak + 3][arow] = aa.w;
        *(float4*)&Bs[bk][bc] = ba;
        __syncthreads();
#pragma unroll
        for (int kk = 0; kk < 16; kk++) {
            float4 a = *(const float4*)&As[kk][ty * 4];
            float4 b = *(const float4*)&Bs[kk][tx * 4];
            float av[4] = {a.x, a.y, a.z, a.w};
            float bv[4] = {b.x, b.y, b.z, b.w};
#pragma unroll
            for (int i = 0; i < 4; i++)
#pragma unroll
                for (int j = 0; j < 4; j++) acc[i][j] += av[i] * bv[j];
        }
    }

#pragma unroll
    for (int i = 0; i < 4; i++) {
        const int r = row0 + ty * 4 + i;
        float4 o = make_float4(acc[i][0], acc[i][1], acc[i][2], acc[i][3]);
        *(float4*)(out + (size_t)r * HDIM + hc0 + tx * 4) = o;
    }
}

// ---------------- routed down: part[slot] = act[slot] @ down_e  (no atomics) ----------------
__global__ __launch_bounds__(256) void expert_down_kernel(const float* __restrict__ dw) { // [E,I,H]
    __shared__ float As[16][68];
    __shared__ float Bs[16][64];

    const int e  = blockIdx.x >> 4;
    const int hc = blockIdx.x & 15;
    const int tc = blockIdx.y;
    const int n  = g_count[e];
    const int row0 = tc * 64;
    if (row0 >= n) return;

    const int tid = threadIdx.x;
    const int tx = tid & 15, ty = tid >> 4;
    const int hc0 = hc * 64;

    const float* A = g_act + (size_t)e * T_TOK * IDIM;
    const float* B = dw + (size_t)e * IDIM * HDIM;

    const int arow = tid >> 2;
    const int ak   = (tid & 3) * 4;
    const int bk   = tid >> 4;
    const int bc   = (tid & 15) * 4;

    float acc[4][4] = {};

    for (int k0 = 0; k0 < IDIM; k0 += 16) {
        float4 aa = *(const float4*)(A + (size_t)(row0 + arow) * IDIM + k0 + ak);
        float4 ba = *(const float4*)(B + (size_t)(k0 + bk) * HDIM + hc0 + bc);
        __syncthreads();
        As[ak + 0][arow] = aa.x; As[ak + 1][arow] = aa.y;
        As[ak + 2][arow] = aa.z; As[ak + 3][arow] = aa.w;
        *(float4*)&Bs[bk][bc] = ba;
        __syncthreads();
#pragma unroll
        for (int kk = 0; kk < 16; kk++) {
            float4 a = *(const float4*)&As[kk][ty * 4];
            float4 b = *(const float4*)&Bs[kk][tx * 4];
            float av[4] = {a.x, a.y, a.z, a.w};
            float bv[4] = {b.x, b.y, b.z, b.w};
#pragma unroll
            for (int i = 0; i < 4; i++)
#pragma unroll
                for (int j = 0; j < 4; j++) acc[i][j] += av[i] * bv[j];
        }
    }

    // NOTE: garbage rows (>= n) in act may produce garbage partials; those slots
    // are never referenced by gather (tok2slot only points at valid slots).
    float* Cbase = g_part + ((size_t)e * T_TOK + row0) * HDIM + hc0;
#pragma unroll
    for (int i = 0; i < 4; i++) {
        const int r = ty * 4 + i;
        float4 o = make_float4(acc[i][0], acc[i][1], acc[i][2], acc[i][3]);
        *(float4*)(Cbase + (size_t)r * HDIM + tx * 4) = o;
    }
}

// ---------------- gather: out[t] = shared[t] + sum_k part[slot(t,k)] ----------------
__global__ void gather_kernel(float* __restrict__ out) {
    __shared__ int slots[TOPK];
    const int t = blockIdx.x;
    if (threadIdx.x < TOPK) slots[threadIdx.x] = g_tok2slot[t * TOPK + threadIdx.x];
    __syncthreads();
    const int h = threadIdx.x * 4; // 256 threads * 4 = 1024 = HDIM
    float4 acc = *(float4*)(out + (size_t)t * HDIM + h);
#pragma unroll
    for (int k = 0; k < TOPK; k++) {
        const float4 p = *(const float4*)(g_part + (size_t)slots[k] * HDIM + h);
        acc.x += p.x; acc.y += p.y; acc.z += p.z; acc.w += p.w;
    }
    *(float4*)(out + (size_t)t * HDIM + h) = acc;
}

// ---------------- launch ----------------
extern "C" void kernel_launch(void* const* d_in, const int* in_sizes, int n_in,
                              void* d_out, int out_size) {
    const float* x  = (const float*)d_in[0]; // [B,S,H] -> [1024,1024]
    const float* rw = (const float*)d_in[1]; // [H,E]
    const float* sg = (const float*)d_in[2]; // [H,I]
    const float* su = (const float*)d_in[3]; // [H,I]
    const float* sd = (const float*)d_in[4]; // [I,H]
    const float* eg = (const float*)d_in[5]; // [E,H,I]
    const float* eu = (const float*)d_in[6]; // [E,H,I]
    const float* ed = (const float*)d_in[7]; // [E,I,H]
    float* out = (float*)d_out;

    zero_counts_kernel<<<1, 64>>>();
    router_kernel<<<T_TOK, 64>>>(x, rw);
    shared_gateup_kernel<<<dim3(IDIM / 64, T_TOK / 64), 256>>>(x, sg, su);
    shared_down_kernel<<<dim3(HDIM / 64, T_TOK / 64), 256>>>(sd, out);
    expert_gateup_kernel<<<dim3(NEXP * (IDIM / 64), T_TOK / 64), 256>>>(x, eg, eu);
    expert_down_kernel<<<dim3(NEXP * (HDIM / 64), T_TOK / 64), 256>>>(ed);
    gather_kernel<<<T_TOK, 256>>>(out);
}

// round 3
// speedup vs baseline: 1.7183x; 1.7183x over previous
#include <cuda_runtime.h>
#include <cuda_bf16.h>
#include <math.h>
#include <stdint.h>

#define T_TOK 1024
#define HDIM  1024
#define IDIM  512
#define NEXP  64
#define TOPK  8

// ================= scratch (static device globals; no allocation) =================
__device__ int   g_count[NEXP];
__device__ int   g_assign_tok[NEXP * T_TOK];
__device__ float g_assign_w[NEXP * T_TOK];
__device__ int   g_tok2slot[T_TOK * TOPK];
__device__ __nv_bfloat16 g_xhi[T_TOK * HDIM];
__device__ __nv_bfloat16 g_xlo[T_TOK * HDIM];
__device__ __nv_bfloat16 g_sact_hi[T_TOK * IDIM];
__device__ __nv_bfloat16 g_sact_lo[T_TOK * IDIM];
__device__ __nv_bfloat16 g_act_hi[(size_t)NEXP * T_TOK * IDIM];
__device__ __nv_bfloat16 g_act_lo[(size_t)NEXP * T_TOK * IDIM];
__device__ float g_part[(size_t)NEXP * T_TOK * HDIM];

// ================= warp-MMA primitives (sm_80 PTX, legal on base sm_103 target) =====
__device__ __forceinline__ uint32_t smem_u32(const void* p) {
    uint32_t a;
    asm("{ .reg .u64 t; cvta.to.shared.u64 t, %1; cvt.u32.u64 %0, t; }" : "=r"(a) : "l"(p));
    return a;
}

__device__ __forceinline__ void ldsm4(uint32_t* r, uint32_t a) {
    asm volatile("ldmatrix.sync.aligned.m8n8.x4.shared.b16 {%0,%1,%2,%3}, [%4];"
                 : "=r"(r[0]), "=r"(r[1]), "=r"(r[2]), "=r"(r[3]) : "r"(a));
}
__device__ __forceinline__ void ldsm2t(uint32_t* r, uint32_t a) {
    asm volatile("ldmatrix.sync.aligned.m8n8.x2.trans.shared.b16 {%0,%1}, [%2];"
                 : "=r"(r[0]), "=r"(r[1]) : "r"(a));
}
__device__ __forceinline__ void mma16816(float* c, const uint32_t* a, const uint32_t* b) {
    asm volatile(
        "mma.sync.aligned.m16n8k16.row.col.f32.bf16.bf16.f32 "
        "{%0,%1,%2,%3}, {%4,%5,%6,%7}, {%8,%9}, {%0,%1,%2,%3};"
        : "+f"(c[0]), "+f"(c[1]), "+f"(c[2]), "+f"(c[3])
        : "r"(a[0]), "r"(a[1]), "r"(a[2]), "r"(a[3]), "r"(b[0]), "r"(b[1]));
}

// pitches (bytes), both multiples of 16
#define A_PITCH 80    // 32 bf16 (64B) + 16B pad
#define B_PITCH 144   // 64 bf16 (128B) + 16B pad

// B stage: W[k0..k0+32)[n0..n0+64) fp32 -> bf16 hi/lo in smem [k][n]
__device__ __forceinline__ void stage_b(const float* __restrict__ W, int ld, int k0, int n0,
                                        char* bh, char* bl, int tid) {
    const int r  = tid >> 3;
    const int c8 = (tid & 7) * 8;
    const float* src = W + (size_t)(k0 + r) * ld + n0 + c8;
    const float4 w0 = *(const float4*)src;
    const float4 w1 = *(const float4*)(src + 4);
    const float f[8] = {w0.x, w0.y, w0.z, w0.w, w1.x, w1.y, w1.z, w1.w};
    uint32_t hv[4], lv[4];
#pragma unroll
    for (int j = 0; j < 4; j++) {
        __nv_bfloat162 h = __floats2bfloat162_rn(f[2 * j], f[2 * j + 1]);
        const float r0 = f[2 * j]     - __bfloat162float(h.x);
        const float r1 = f[2 * j + 1] - __bfloat162float(h.y);
        __nv_bfloat162 l = __floats2bfloat162_rn(r0, r1);
        hv[j] = *(uint32_t*)&h;
        lv[j] = *(uint32_t*)&l;
    }
    *(uint4*)(bh + r * B_PITCH + c8 * 2) = make_uint4(hv[0], hv[1], hv[2], hv[3]);
    *(uint4*)(bl + r * B_PITCH + c8 * 2) = make_uint4(lv[0], lv[1], lv[2], lv[3]);
}

// ================= init / router =================
__global__ void zero_counts_kernel() {
    if (threadIdx.x < NEXP) g_count[threadIdx.x] = 0;
}

__global__ void router_kernel(const float* __restrict__ x, const float* __restrict__ rw) {
    __shared__ float xs[HDIM];
    __shared__ float aff[NEXP];
    const int t = blockIdx.x;
    const int tid = threadIdx.x; // 64 threads
    for (int h = tid; h < HDIM; h += 64) xs[h] = x[(size_t)t * HDIM + h];
    __syncthreads();
    float acc = 0.f;
#pragma unroll 8
    for (int h = 0; h < HDIM; h++) acc += xs[h] * rw[h * NEXP + tid];
    aff[tid] = 1.f / (1.f + expf(-acc));
    __syncthreads();
    if (tid == 0) {
        float tmp[NEXP];
#pragma unroll
        for (int i = 0; i < NEXP; i++) tmp[i] = aff[i];
        int idx[TOPK]; float sc[TOPK]; float s = 0.f;
        for (int k = 0; k < TOPK; k++) {
            int bi = 0; float bv = -1e30f;
            for (int i = 0; i < NEXP; i++) if (tmp[i] > bv) { bv = tmp[i]; bi = i; }
            idx[k] = bi; sc[k] = bv; tmp[bi] = -1e30f; s += bv;
        }
        const float inv = 1.f / (s + 1e-9f);
        for (int k = 0; k < TOPK; k++) {
            const int e = idx[k];
            const int slot = atomicAdd(&g_count[e], 1);
            g_assign_tok[e * T_TOK + slot] = t;
            g_assign_w[e * T_TOK + slot]   = sc[k] * inv;
            g_tok2slot[t * TOPK + k]       = e * T_TOK + slot;
        }
    }
}

// ================= x -> bf16 hi/lo split =================
__global__ void splitx_kernel(const float* __restrict__ x) {
    const int i = (blockIdx.x * 256 + threadIdx.x) * 4;
    float4 v = *(const float4*)(x + i);
    float a[4] = {v.x, v.y, v.z, v.w};
    __nv_bfloat162 h01 = __floats2bfloat162_rn(a[0], a[1]);
    __nv_bfloat162 h23 = __floats2bfloat162_rn(a[2], a[3]);
    float l0 = a[0] - __bfloat162float(h01.x);
    float l1 = a[1] - __bfloat162float(h01.y);
    float l2 = a[2] - __bfloat162float(h23.x);
    float l3 = a[3] - __bfloat162float(h23.y);
    __nv_bfloat162 q01 = __floats2bfloat162_rn(l0, l1);
    __nv_bfloat162 q23 = __floats2bfloat162_rn(l2, l3);
    uint2 hv, lv;
    hv.x = *(uint32_t*)&h01; hv.y = *(uint32_t*)&h23;
    lv.x = *(uint32_t*)&q01; lv.y = *(uint32_t*)&q23;
    *(uint2*)(g_xhi + i) = hv;
    *(uint2*)(g_xlo + i) = lv;
}

// ================= fused gate/up GEMM (HMMA, split-bf16 3-pass) =================
// grid: (IDIM/64, 8 mtiles, 65 experts [64 = shared]); 256 threads
__global__ __launch_bounds__(256, 2) void gateup_kernel(
    const float* __restrict__ eg, const float* __restrict__ eu,
    const float* __restrict__ sg, const float* __restrict__ su)
{
    __shared__ __align__(16) char sAh[128 * A_PITCH];
    __shared__ __align__(16) char sAl[128 * A_PITCH];
    __shared__ __align__(16) char sBgh[32 * B_PITCH];
    __shared__ __align__(16) char sBgl[32 * B_PITCH];
    __shared__ __align__(16) char sBuh[32 * B_PITCH];
    __shared__ __align__(16) char sBul[32 * B_PITCH];
    __shared__ int toks[128];

    const int e = blockIdx.z;
    const bool shared_e = (e == NEXP);
    const int n0 = blockIdx.x * 64;
    const int row0 = blockIdx.y * 128;
    const int n = shared_e ? T_TOK : g_count[e];
    if (row0 >= n) return;

    const int tid = threadIdx.x;
    const int wid = tid >> 5, lane = tid & 31;
    const int wm = wid >> 1, wn = wid & 1;

    if (tid < 128) {
        const int r = row0 + tid;
        toks[tid] = shared_e ? r : ((r < n) ? g_assign_tok[e * T_TOK + r] : 0);
    }
    __syncthreads();

    const float* WG = shared_e ? sg : (eg + (size_t)e * HDIM * IDIM);
    const float* WU = shared_e ? su : (eu + (size_t)e * HDIM * IDIM);

    const int ar = tid >> 1, ah_ = tid & 1;
    const int myTok = toks[ar];

    float gacc[2][4][4] = {};
    float uacc[2][4][4] = {};

    const uint32_t uAh = smem_u32(sAh), uAl = smem_u32(sAl);
    const uint32_t uBgh = smem_u32(sBgh), uBgl = smem_u32(sBgl);
    const uint32_t uBuh = smem_u32(sBuh), uBul = smem_u32(sBul);

    for (int k0 = 0; k0 < HDIM; k0 += 32) {
        // stage A (gathered bf16 hi/lo token rows)
        {
            const size_t base = (size_t)myTok * HDIM + k0 + ah_ * 16;
            const int dst = ar * A_PITCH + ah_ * 32;
            *(uint4*)(sAh + dst)      = *(const uint4*)(g_xhi + base);
            *(uint4*)(sAh + dst + 16) = *(const uint4*)(g_xhi + base + 8);
            *(uint4*)(sAl + dst)      = *(const uint4*)(g_xlo + base);
            *(uint4*)(sAl + dst + 16) = *(const uint4*)(g_xlo + base + 8);
        }
        stage_b(WG, IDIM, k0, n0, sBgh, sBgl, tid);
        stage_b(WU, IDIM, k0, n0, sBuh, sBul, tid);
        __syncthreads();

#pragma unroll
        for (int ks = 0; ks < 2; ks++) {
            uint32_t afh[2][4], afl[2][4];
#pragma unroll
            for (int mi = 0; mi < 2; mi++) {
                const uint32_t aoff = (uint32_t)((wm * 32 + mi * 16 + (lane & 15)) * A_PITCH
                                                 + ks * 32 + (lane >> 4) * 16);
                ldsm4(afh[mi], uAh + aoff);
                ldsm4(afl[mi], uAl + aoff);
            }
#pragma unroll
            for (int ni = 0; ni < 4; ni++) {
                const uint32_t boff = (uint32_t)((ks * 16 + (lane & 15)) * B_PITCH
                                                 + (wn * 32 + ni * 8) * 2);
                uint32_t bh[2], bl[2];
                ldsm2t(bh, uBgh + boff);
                ldsm2t(bl, uBgl + boff);
#pragma unroll
                for (int mi = 0; mi < 2; mi++) {
                    mma16816(gacc[mi][ni], afh[mi], bh);
                    mma16816(gacc[mi][ni], afh[mi], bl);
                    mma16816(gacc[mi][ni], afl[mi], bh);
                }
                ldsm2t(bh, uBuh + boff);
                ldsm2t(bl, uBul + boff);
#pragma unroll
                for (int mi = 0; mi < 2; mi++) {
                    mma16816(uacc[mi][ni], afh[mi], bh);
                    mma16816(uacc[mi][ni], afh[mi], bl);
                    mma16816(uacc[mi][ni], afl[mi], bh);
                }
            }
        }
        __syncthreads();
    }

    // epilogue: act = silu(g)*u*w -> bf16 hi/lo
    int nn = n - row0; if (nn > 128) nn = 128;
#pragma unroll
    for (int mi = 0; mi < 2; mi++) {
#pragma unroll
        for (int p = 0; p < 2; p++) {
            const int m = wm * 32 + mi * 16 + (lane >> 2) + p * 8;
            if (m >= nn) continue;
            float w = 1.f;
            __nv_bfloat16 *dh, *dl;
            if (shared_e) {
                dh = g_sact_hi + (size_t)(row0 + m) * IDIM;
                dl = g_sact_lo + (size_t)(row0 + m) * IDIM;
            } else {
                w = g_assign_w[e * T_TOK + row0 + m];
                const size_t slot = (size_t)e * T_TOK + row0 + m;
                dh = g_act_hi + slot * IDIM;
                dl = g_act_lo + slot * IDIM;
            }
            const int ncb = n0 + wn * 32 + (lane & 3) * 2;
#pragma unroll
            for (int ni = 0; ni < 4; ni++) {
                const float g0 = gacc[mi][ni][p * 2 + 0];
                const float g1 = gacc[mi][ni][p * 2 + 1];
                const float u0 = uacc[mi][ni][p * 2 + 0];
                const float u1 = uacc[mi][ni][p * 2 + 1];
                const float a0 = g0 / (1.f + __expf(-g0)) * u0 * w;
                const float a1 = g1 / (1.f + __expf(-g1)) * u1 * w;
                __nv_bfloat162 h = __floats2bfloat162_rn(a0, a1);
                const float l0 = a0 - __bfloat162float(h.x);
                const float l1 = a1 - __bfloat162float(h.y);
                __nv_bfloat162 l = __floats2bfloat162_rn(l0, l1);
                *(uint32_t*)(dh + ncb + ni * 8) = *(uint32_t*)&h;
                *(uint32_t*)(dl + ncb + ni * 8) = *(uint32_t*)&l;
            }
        }
    }
}

// ================= down GEMM (HMMA, split-bf16 3-pass) =================
// grid: (HDIM/64, 8 mtiles, 65 experts [64 = shared]); 256 threads
__global__ __launch_bounds__(256, 2) void down_kernel(
    const float* __restrict__ ed, const float* __restrict__ sd,
    float* __restrict__ out)
{
    __shared__ __align__(16) char sAh[128 * A_PITCH];
    __shared__ __align__(16) char sAl[128 * A_PITCH];
    __shared__ __align__(16) char sBh[32 * B_PITCH];
    __shared__ __align__(16) char sBl[32 * B_PITCH];

    const int e = blockIdx.z;
    const bool shared_e = (e == NEXP);
    const int n0 = blockIdx.x * 64;
    const int row0 = blockIdx.y * 128;
    const int n = shared_e ? T_TOK : g_count[e];
    if (row0 >= n) return;

    const int tid = threadIdx.x;
    const int wid = tid >> 5, lane = tid & 31;
    const int wm = wid >> 1, wn = wid & 1;

    const float* W = shared_e ? sd : (ed + (size_t)e * IDIM * HDIM);
    const __nv_bfloat16* Ah = shared_e ? (g_sact_hi + (size_t)row0 * IDIM)
                                       : (g_act_hi + ((size_t)e * T_TOK + row0) * IDIM);
    const __nv_bfloat16* Al = shared_e ? (g_sact_lo + (size_t)row0 * IDIM)
                                       : (g_act_lo + ((size_t)e * T_TOK + row0) * IDIM);

    const int ar = tid >> 1, ah_ = tid & 1;
    float acc[2][4][4] = {};

    const uint32_t uAh = smem_u32(sAh), uAl = smem_u32(sAl);
    const uint32_t uBh = smem_u32(sBh), uBl = smem_u32(sBl);

    for (int k0 = 0; k0 < IDIM; k0 += 32) {
        {
            const size_t base = (size_t)ar * IDIM + k0 + ah_ * 16;
            const int dst = ar * A_PITCH + ah_ * 32;
            *(uint4*)(sAh + dst)      = *(const uint4*)(Ah + base);
            *(uint4*)(sAh + dst + 16) = *(const uint4*)(Ah + base + 8);
            *(uint4*)(sAl + dst)      = *(const uint4*)(Al + base);
            *(uint4*)(sAl + dst + 16) = *(const uint4*)(Al + base + 8);
        }
        stage_b(W, HDIM, k0, n0, sBh, sBl, tid);
        __syncthreads();

#pragma unroll
        for (int ks = 0; ks < 2; ks++) {
            uint32_t afh[2][4], afl[2][4];
#pragma unroll
            for (int mi = 0; mi < 2; mi++) {
                const uint32_t aoff = (uint32_t)((wm * 32 + mi * 16 + (lane & 15)) * A_PITCH
                                                 + ks * 32 + (lane >> 4) * 16);
                ldsm4(afh[mi], uAh + aoff);
                ldsm4(afl[mi], uAl + aoff);
            }
#pragma unroll
            for (int ni = 0; ni < 4; ni++) {
                const uint32_t boff = (uint32_t)((ks * 16 + (lane & 15)) * B_PITCH
                                                 + (wn * 32 + ni * 8) * 2);
                uint32_t bh[2], bl[2];
                ldsm2t(bh, uBh + boff);
                ldsm2t(bl, uBl + boff);
#pragma unroll
                for (int mi = 0; mi < 2; mi++) {
                    mma16816(acc[mi][ni], afh[mi], bh);
                    mma16816(acc[mi][ni], afh[mi], bl);
                    mma16816(acc[mi][ni], afl[mi], bh);
                }
            }
        }
        __syncthreads();
    }

    // epilogue: fp32 stores (shared -> out, routed -> per-assignment partials)
#pragma unroll
    for (int mi = 0; mi < 2; mi++) {
#pragma unroll
        for (int p = 0; p < 2; p++) {
            const int m = wm * 32 + mi * 16 + (lane >> 2) + p * 8;
            float* dst = shared_e ? (out + (size_t)(row0 + m) * HDIM)
                                  : (g_part + ((size_t)e * T_TOK + row0 + m) * HDIM);
            const int ncb = n0 + wn * 32 + (lane & 3) * 2;
#pragma unroll
            for (int ni = 0; ni < 4; ni++) {
                float2 o = make_float2(acc[mi][ni][p * 2 + 0], acc[mi][ni][p * 2 + 1]);
                *(float2*)(dst + ncb + ni * 8) = o;
            }
        }
    }
}

// ================= gather: out[t] += sum_k part[slot(t,k)] =================
__global__ void gather_kernel(float* __restrict__ out) {
    __shared__ int slots[TOPK];
    const int t = blockIdx.x;
    if (threadIdx.x < TOPK) slots[threadIdx.x] = g_tok2slot[t * TOPK + threadIdx.x];
    __syncthreads();
    const int h = threadIdx.x * 4;
    float4 acc = *(float4*)(out + (size_t)t * HDIM + h);
#pragma unroll
    for (int k = 0; k < TOPK; k++) {
        const float4 p = *(const float4*)(g_part + (size_t)slots[k] * HDIM + h);
        acc.x += p.x; acc.y += p.y; acc.z += p.z; acc.w += p.w;
    }
    *(float4*)(out + (size_t)t * HDIM + h) = acc;
}

// ================= launch =================
extern "C" void kernel_launch(void* const* d_in, const int* in_sizes, int n_in,
                              void* d_out, int out_size) {
    const float* x  = (const float*)d_in[0]; // [B,S,H] -> [1024,1024]
    const float* rw = (const float*)d_in[1]; // [H,E]
    const float* sg = (const float*)d_in[2]; // [H,I]
    const float* su = (const float*)d_in[3]; // [H,I]
    const float* sd = (const float*)d_in[4]; // [I,H]
    const float* eg = (const float*)d_in[5]; // [E,H,I]
    const float* eu = (const float*)d_in[6]; // [E,H,I]
    const float* ed = (const float*)d_in[7]; // [E,I,H]
    float* out = (float*)d_out;

    zero_counts_kernel<<<1, 64>>>();
    router_kernel<<<T_TOK, 64>>>(x, rw);
    splitx_kernel<<<1024, 256>>>(x);
    gateup_kernel<<<dim3(IDIM / 64, T_TOK / 128, NEXP + 1), 256>>>(eg, eu, sg, su);
    down_kernel<<<dim3(HDIM / 64, T_TOK / 128, NEXP + 1), 256>>>(ed, sd, out);
    gather_kernel<<<T_TOK, 256>>>(out);
}